// round 1
// baseline (speedup 1.0000x reference)
#include <cuda_runtime.h>
#include <math.h>

#define BB   2
#define SS   2048
#define DD   1024
#define HH   16
#define DHH  64
#define NROW (BB*SS)      // 4096 flattened (b,s) rows
#define KT   (SS/64)      // 32 key tiles

// Scratch (allocation-free rule: __device__ globals)
__device__ float g_q[(size_t)BB*HH*SS*DHH];   // 16 MB
__device__ float g_k[(size_t)BB*HH*SS*DHH];   // 16 MB
__device__ float g_v[(size_t)BB*HH*SS*DHH];   // 16 MB
__device__ float g_ctx[(size_t)NROW*DD];      // 16 MB

// ---------------------------------------------------------------------------
// Kernel 1: fused per-head QKV projection.
// out[b,h,s,e] = sum_d x[b,s,d] * W[h,d,e] + bias[h,e]
// grid = (NROW/64, H, 3), block = 256, 64x64 output tile, 4x4 per thread.
// ---------------------------------------------------------------------------
__global__ __launch_bounds__(256) void qkv_kernel(
    const float* __restrict__ x,
    const float* __restrict__ Wq, const float* __restrict__ bq,
    const float* __restrict__ Wk, const float* __restrict__ bk,
    const float* __restrict__ Wv, const float* __restrict__ bv)
{
    __shared__ float As[64][65];   // x tile, padded (scalar broadcast reads)
    __shared__ float Bs[64][64];   // W tile, natural [k][n] layout -> LDS.128

    const int h = blockIdx.y;
    const float* W; const float* bias; float* out;
    if (blockIdx.z == 0)      { W = Wq; bias = bq; out = g_q; }
    else if (blockIdx.z == 1) { W = Wk; bias = bk; out = g_k; }
    else                      { W = Wv; bias = bv; out = g_v; }
    W    += (size_t)h * DD * DHH;
    bias += h * DHH;

    const int tid = threadIdx.x;
    const int ty = tid >> 4, tx = tid & 15;
    const int r0 = blockIdx.x * 64;

    float acc[4][4] = {};

    for (int kk = 0; kk < DD; kk += 64) {
        #pragma unroll
        for (int l = 0; l < 4; l++) {
            int idx = tid + l * 256;       // 1024 float4 slots
            int i = idx >> 4;
            int j = (idx & 15) << 2;
            float4 a4 = *reinterpret_cast<const float4*>(x + (size_t)(r0 + i) * DD + kk + j);
            As[i][j+0] = a4.x; As[i][j+1] = a4.y; As[i][j+2] = a4.z; As[i][j+3] = a4.w;
            *reinterpret_cast<float4*>(&Bs[i][j]) =
                *reinterpret_cast<const float4*>(W + (size_t)(kk + i) * DHH + j);
        }
        __syncthreads();

        #pragma unroll 8
        for (int k = 0; k < 64; k++) {
            float a[4];
            a[0] = As[ty*4+0][k]; a[1] = As[ty*4+1][k];
            a[2] = As[ty*4+2][k]; a[3] = As[ty*4+3][k];
            float4 b4 = *reinterpret_cast<float4*>(&Bs[k][tx*4]);
            float bb[4] = {b4.x, b4.y, b4.z, b4.w};
            #pragma unroll
            for (int i = 0; i < 4; i++)
                #pragma unroll
                for (int j = 0; j < 4; j++)
                    acc[i][j] = fmaf(a[i], bb[j], acc[i][j]);
        }
        __syncthreads();
    }

    // epilogue: bias + store into [B,H,S,DH]
    #pragma unroll
    for (int i = 0; i < 4; i++) {
        int r = r0 + ty*4 + i;
        int b = r / SS, s = r % SS;
        float4 o4;
        o4.x = acc[i][0] + bias[tx*4+0];
        o4.y = acc[i][1] + bias[tx*4+1];
        o4.z = acc[i][2] + bias[tx*4+2];
        o4.w = acc[i][3] + bias[tx*4+3];
        *reinterpret_cast<float4*>(out + ((((size_t)b*HH + h)*SS + s)*DHH) + tx*4) = o4;
    }
}

// ---------------------------------------------------------------------------
// Kernel 2: flash-attention (online softmax), fp32.
// grid = (S/64, H, B), block = 256. Per block: 64 queries x full key loop.
// O accumulator (64x64) lives in registers, 4x4 per thread.
// ---------------------------------------------------------------------------
#define ATTN_SMEM_FLOATS (64*64 + 64*65 + 64*64 + 64*65 + 3*64)
#define ATTN_SMEM_BYTES  (ATTN_SMEM_FLOATS * 4)

__global__ __launch_bounds__(256) void attn_kernel()
{
    extern __shared__ float sm[];
    float* Qs   = sm;                  // [64][64]  (pre-scaled by 1/8)
    float* Ks   = Qs  + 64*64;         // [64][65]  padded: QK^T B-operand
    float* Vs   = Ks  + 64*65;         // [64][64]  natural: LDS.128 in PV
    float* Ps   = Vs  + 64*64;         // [64][65]  scores / probs tile
    float* m_s  = Ps  + 64*65;         // [64] running max
    float* l_s  = m_s + 64;            // [64] running sum
    float* cf_s = l_s + 64;            // [64] correction factor

    const int qt = blockIdx.x, h = blockIdx.y, b = blockIdx.z;
    const int tid = threadIdx.x;
    const int ty = tid >> 4, tx = tid & 15;

    const size_t head_off = (((size_t)b*HH + h)*SS) * DHH;
    const float* qbase = g_q + head_off;
    const float* kbase = g_k + head_off;
    const float* vbase = g_v + head_off;

    // load Q tile (scaled by 1/sqrt(DH) = 0.125)
    #pragma unroll
    for (int l = 0; l < 4; l++) {
        int idx = tid + l * 256;
        int i = idx >> 4;
        int j = (idx & 15) << 2;
        float4 q4 = *reinterpret_cast<const float4*>(qbase + (size_t)(qt*64 + i)*DHH + j);
        Qs[i*64+j+0] = q4.x * 0.125f; Qs[i*64+j+1] = q4.y * 0.125f;
        Qs[i*64+j+2] = q4.z * 0.125f; Qs[i*64+j+3] = q4.w * 0.125f;
    }
    if (tid < 64) { m_s[tid] = -INFINITY; l_s[tid] = 0.f; }

    float o[4][4] = {};

    for (int kt = 0; kt < KT; kt++) {
        // load K (padded) and V (natural) tiles
        #pragma unroll
        for (int l = 0; l < 4; l++) {
            int idx = tid + l * 256;
            int i = idx >> 4;
            int j = (idx & 15) << 2;
            float4 k4 = *reinterpret_cast<const float4*>(kbase + (size_t)(kt*64 + i)*DHH + j);
            Ks[i*65+j+0] = k4.x; Ks[i*65+j+1] = k4.y;
            Ks[i*65+j+2] = k4.z; Ks[i*65+j+3] = k4.w;
            *reinterpret_cast<float4*>(&Vs[i*64+j]) =
                *reinterpret_cast<const float4*>(vbase + (size_t)(kt*64 + i)*DHH + j);
        }
        __syncthreads();

        // S = (Q/8) K^T  -> Ps
        {
            float sacc[4][4] = {};
            #pragma unroll 8
            for (int k = 0; k < 64; k++) {
                float a[4], bb[4];
                a[0] = Qs[(ty*4+0)*64 + k]; a[1] = Qs[(ty*4+1)*64 + k];
                a[2] = Qs[(ty*4+2)*64 + k]; a[3] = Qs[(ty*4+3)*64 + k];
                bb[0] = Ks[(tx*4+0)*65 + k]; bb[1] = Ks[(tx*4+1)*65 + k];
                bb[2] = Ks[(tx*4+2)*65 + k]; bb[3] = Ks[(tx*4+3)*65 + k];
                #pragma unroll
                for (int i = 0; i < 4; i++)
                    #pragma unroll
                    for (int j = 0; j < 4; j++)
                        sacc[i][j] = fmaf(a[i], bb[j], sacc[i][j]);
            }
            #pragma unroll
            for (int i = 0; i < 4; i++)
                #pragma unroll
                for (int j = 0; j < 4; j++)
                    Ps[(ty*4+i)*65 + tx*4+j] = sacc[i][j];
        }
        __syncthreads();

        // online softmax update: 4 threads per row (lane-aligned groups of 4)
        {
            int row = tid >> 2, g = tid & 3;
            float* pr = Ps + row*65 + g*16;
            float m_old = m_s[row];
            float tmax = pr[0];
            #pragma unroll
            for (int c = 1; c < 16; c++) tmax = fmaxf(tmax, pr[c]);
            tmax = fmaxf(tmax, __shfl_xor_sync(0xffffffffu, tmax, 1));
            tmax = fmaxf(tmax, __shfl_xor_sync(0xffffffffu, tmax, 2));
            float newm = fmaxf(m_old, tmax);
            float psum = 0.f;
            #pragma unroll
            for (int c = 0; c < 16; c++) {
                float p = __expf(pr[c] - newm);
                pr[c] = p;
                psum += p;
            }
            psum += __shfl_xor_sync(0xffffffffu, psum, 1);
            psum += __shfl_xor_sync(0xffffffffu, psum, 2);
            if (g == 0) {
                float cf = __expf(m_old - newm);   // 0 on first tile (m_old = -inf)
                cf_s[row] = cf;
                m_s[row]  = newm;
                l_s[row]  = l_s[row]*cf + psum;
            }
        }
        __syncthreads();

        // O = O*cf + P @ V
        {
            float cf[4];
            cf[0] = cf_s[ty*4+0]; cf[1] = cf_s[ty*4+1];
            cf[2] = cf_s[ty*4+2]; cf[3] = cf_s[ty*4+3];
            #pragma unroll
            for (int i = 0; i < 4; i++)
                #pragma unroll
                for (int j = 0; j < 4; j++)
                    o[i][j] *= cf[i];

            #pragma unroll 8
            for (int k = 0; k < 64; k++) {
                float a[4];
                a[0] = Ps[(ty*4+0)*65 + k]; a[1] = Ps[(ty*4+1)*65 + k];
                a[2] = Ps[(ty*4+2)*65 + k]; a[3] = Ps[(ty*4+3)*65 + k];
                float4 v4 = *reinterpret_cast<float4*>(&Vs[k*64 + tx*4]);
                float bb[4] = {v4.x, v4.y, v4.z, v4.w};
                #pragma unroll
                for (int i = 0; i < 4; i++)
                    #pragma unroll
                    for (int j = 0; j < 4; j++)
                        o[i][j] = fmaf(a[i], bb[j], o[i][j]);
            }
        }
        __syncthreads();
    }

    // epilogue: normalize and write ctx in [B,S,H*DH] layout for out-proj
    #pragma unroll
    for (int i = 0; i < 4; i++) {
        int row = ty*4 + i;
        float inv = 1.f / l_s[row];
        int srow = qt*64 + row;
        float4 o4 = make_float4(o[i][0]*inv, o[i][1]*inv, o[i][2]*inv, o[i][3]*inv);
        *reinterpret_cast<float4*>(g_ctx + ((size_t)b*SS + srow)*DD + h*DHH + tx*4) = o4;
    }
}

// ---------------------------------------------------------------------------
// Kernel 3: output projection  out = ctx @ Wo + bo
// grid = (NROW/64, D/64), block = 256.
// ---------------------------------------------------------------------------
__global__ __launch_bounds__(256) void proj_kernel(
    const float* __restrict__ Wo, const float* __restrict__ bo,
    float* __restrict__ out)
{
    __shared__ float As[64][65];
    __shared__ float Bs[64][64];

    const int tid = threadIdx.x;
    const int ty = tid >> 4, tx = tid & 15;
    const int r0 = blockIdx.x * 64;
    const int n0 = blockIdx.y * 64;

    float acc[4][4] = {};

    for (int kk = 0; kk < DD; kk += 64) {
        #pragma unroll
        for (int l = 0; l < 4; l++) {
            int idx = tid + l * 256;
            int i = idx >> 4;
            int j = (idx & 15) << 2;
            float4 a4 = *reinterpret_cast<const float4*>(g_ctx + (size_t)(r0 + i)*DD + kk + j);
            As[i][j+0] = a4.x; As[i][j+1] = a4.y; As[i][j+2] = a4.z; As[i][j+3] = a4.w;
            *reinterpret_cast<float4*>(&Bs[i][j]) =
                *reinterpret_cast<const float4*>(Wo + (size_t)(kk + i)*DD + n0 + j);
        }
        __syncthreads();

        #pragma unroll 8
        for (int k = 0; k < 64; k++) {
            float a[4];
            a[0] = As[ty*4+0][k]; a[1] = As[ty*4+1][k];
            a[2] = As[ty*4+2][k]; a[3] = As[ty*4+3][k];
            float4 b4 = *reinterpret_cast<float4*>(&Bs[k][tx*4]);
            float bb[4] = {b4.x, b4.y, b4.z, b4.w};
            #pragma unroll
            for (int i = 0; i < 4; i++)
                #pragma unroll
                for (int j = 0; j < 4; j++)
                    acc[i][j] = fmaf(a[i], bb[j], acc[i][j]);
        }
        __syncthreads();
    }

    #pragma unroll
    for (int i = 0; i < 4; i++) {
        int r = r0 + ty*4 + i;
        float4 o4;
        o4.x = acc[i][0] + bo[n0 + tx*4+0];
        o4.y = acc[i][1] + bo[n0 + tx*4+1];
        o4.z = acc[i][2] + bo[n0 + tx*4+2];
        o4.w = acc[i][3] + bo[n0 + tx*4+3];
        *reinterpret_cast<float4*>(out + (size_t)r*DD + n0 + tx*4) = o4;
    }
}

// ---------------------------------------------------------------------------
extern "C" void kernel_launch(void* const* d_in, const int* in_sizes, int n_in,
                              void* d_out, int out_size)
{
    const float* x  = (const float*)d_in[0];
    const float* Wq = (const float*)d_in[1];
    const float* bq = (const float*)d_in[2];
    const float* Wk = (const float*)d_in[3];
    const float* bk = (const float*)d_in[4];
    const float* Wv = (const float*)d_in[5];
    const float* bv = (const float*)d_in[6];
    const float* Wo = (const float*)d_in[7];
    const float* bo = (const float*)d_in[8];
    float* out = (float*)d_out;

    cudaFuncSetAttribute(attn_kernel,
                         cudaFuncAttributeMaxDynamicSharedMemorySize,
                         ATTN_SMEM_BYTES);

    qkv_kernel<<<dim3(NROW/64, HH, 3), 256>>>(x, Wq, bq, Wk, bk, Wv, bv);
    attn_kernel<<<dim3(SS/64, HH, BB), 256, ATTN_SMEM_BYTES>>>();
    proj_kernel<<<dim3(NROW/64, DD/64), 256>>>(Wo, bo, out);
}

// round 8
// speedup vs baseline: 2.2134x; 2.2134x over previous
#include <cuda_runtime.h>
#include <math.h>

#define BB   2
#define SS   2048
#define DD   1024
#define HH   16
#define DHH  64
#define NROW (BB*SS)      // 4096
#define KT   (SS/64)      // 32 key tiles

// Scratch (allocation-free rule: __device__ globals)
__device__ float g_q[(size_t)BB*HH*SS*DHH];
__device__ float g_k[(size_t)BB*HH*SS*DHH];
__device__ float g_v[(size_t)BB*HH*SS*DHH];
__device__ float g_ctx[(size_t)NROW*DD];

// ---------------------------------------------------------------------------
// tf32 helpers
// ---------------------------------------------------------------------------
__device__ __forceinline__ unsigned f2t(float f) {
    unsigned u;
    asm("cvt.rna.tf32.f32 %0, %1;" : "=r"(u) : "f"(f));
    return u;
}

// D += A(16x8) * B(8x8), tf32 inputs, fp32 accum
__device__ __forceinline__ void mma8(float* c, const unsigned* a, unsigned b0, unsigned b1) {
    asm volatile(
        "mma.sync.aligned.m16n8k8.row.col.f32.tf32.tf32.f32 "
        "{%0,%1,%2,%3}, {%4,%5,%6,%7}, {%8,%9}, {%0,%1,%2,%3};"
        : "+f"(c[0]), "+f"(c[1]), "+f"(c[2]), "+f"(c[3])
        : "r"(a[0]), "r"(a[1]), "r"(a[2]), "r"(a[3]), "r"(b0), "r"(b1));
}

// ---------------------------------------------------------------------------
// Kernel 1: fused per-head QKV projection (tensor cores, tf32).
// out[b,h,s,e] = sum_d x[b,s,d] * W[h,d,e] + bias[h,e]
// grid = (NROW/256, H, 3), block = 256 (8 warps). Block tile 256x64.
// Warp tile: 32 rows x 64 cols (mtiles=2, ntiles=8). K-chunks of 32.
// ---------------------------------------------------------------------------
__global__ __launch_bounds__(256) void qkv_kernel(
    const float* __restrict__ x,
    const float* __restrict__ Wq, const float* __restrict__ bq,
    const float* __restrict__ Wk, const float* __restrict__ bk,
    const float* __restrict__ Wv, const float* __restrict__ bv)
{
    __shared__ unsigned A_s[256*36];   // x tile [256 rows][32 k], pad 36, tf32 bits
    __shared__ unsigned B_s[64*36];    // W tile transposed [64 n][32 k], pad 36

    const int h = blockIdx.y;
    const float* W; const float* bias; float* out;
    if (blockIdx.z == 0)      { W = Wq; bias = bq; out = g_q; }
    else if (blockIdx.z == 1) { W = Wk; bias = bk; out = g_k; }
    else                      { W = Wv; bias = bv; out = g_v; }
    W    += (size_t)h * DD * DHH;
    bias += h * DHH;

    const int tid  = threadIdx.x;
    const int wid  = tid >> 5;
    const int lane = tid & 31;
    const int g    = lane >> 2;       // groupID
    const int t    = lane & 3;        // threadID_in_group
    const int r0   = blockIdx.x * 256;

    float acc[2][8][4] = {};

    for (int kk = 0; kk < DD; kk += 32) {
        // --- load X tile 256x32 -> A_s (tf32 bits) ---
        #pragma unroll
        for (int l = 0; l < 8; l++) {
            int idx = tid + l * 256;          // 2048 float4 slots
            int i = idx >> 3;
            int j = (idx & 7) << 2;
            float4 a4 = *reinterpret_cast<const float4*>(x + (size_t)(r0 + i) * DD + kk + j);
            unsigned* p = &A_s[i*36 + j];
            p[0] = f2t(a4.x); p[1] = f2t(a4.y); p[2] = f2t(a4.z); p[3] = f2t(a4.w);
        }
        // --- load W tile 32x64 transposed -> B_s[e][d] ---
        #pragma unroll
        for (int l = 0; l < 2; l++) {
            int idx = tid + l * 256;          // 512 float4 slots
            int d = idx >> 4;                 // 0..31
            int e = (idx & 15) << 2;
            float4 w4 = *reinterpret_cast<const float4*>(W + (size_t)(kk + d) * DHH + e);
            B_s[(e+0)*36 + d] = f2t(w4.x);
            B_s[(e+1)*36 + d] = f2t(w4.y);
            B_s[(e+2)*36 + d] = f2t(w4.z);
            B_s[(e+3)*36 + d] = f2t(w4.w);
        }
        __syncthreads();

        #pragma unroll
        for (int ks = 0; ks < 4; ks++) {
            int k8 = ks * 8;
            unsigned a[2][4];
            #pragma unroll
            for (int mt = 0; mt < 2; mt++) {
                int rb = wid*32 + mt*16 + g;
                a[mt][0] = A_s[(rb  )*36 + k8 + t];
                a[mt][1] = A_s[(rb+8)*36 + k8 + t];
                a[mt][2] = A_s[(rb  )*36 + k8 + t + 4];
                a[mt][3] = A_s[(rb+8)*36 + k8 + t + 4];
            }
            #pragma unroll
            for (int nt = 0; nt < 8; nt++) {
                unsigned b0 = B_s[(nt*8 + g)*36 + k8 + t];
                unsigned b1 = B_s[(nt*8 + g)*36 + k8 + t + 4];
                mma8(acc[0][nt], a[0], b0, b1);
                mma8(acc[1][nt], a[1], b0, b1);
            }
        }
        __syncthreads();
    }

    // epilogue: bias + store into [B,H,S,DH]
    #pragma unroll
    for (int mt = 0; mt < 2; mt++) {
        #pragma unroll
        for (int nt = 0; nt < 8; nt++) {
            int col = nt*8 + 2*t;
            float b0 = bias[col], b1 = bias[col+1];
            int r_lo = r0 + wid*32 + mt*16 + g;
            int r_hi = r_lo + 8;
            {
                int b = r_lo >> 11, s = r_lo & 2047;
                float2 o = make_float2(acc[mt][nt][0] + b0, acc[mt][nt][1] + b1);
                *reinterpret_cast<float2*>(out + ((((size_t)b*HH + h)*SS + s)*DHH) + col) = o;
            }
            {
                int b = r_hi >> 11, s = r_hi & 2047;
                float2 o = make_float2(acc[mt][nt][2] + b0, acc[mt][nt][3] + b1);
                *reinterpret_cast<float2*>(out + ((((size_t)b*HH + h)*SS + s)*DHH) + col) = o;
            }
        }
    }
}

// ---------------------------------------------------------------------------
// Kernel 2: flash attention, tf32 tensor cores.
// grid = (S/128, H, B), block = 256 (8 warps). Each warp owns 16 query rows
// (full 64-key coverage -> warp-local softmax). Online softmax over 32 key
// tiles of 64. Q fragments live in registers for the whole kernel.
// ---------------------------------------------------------------------------
#define ATTN_SMEM_WORDS (64*68 + 64*72 + 128*68)
#define ATTN_SMEM_BYTES (ATTN_SMEM_WORDS * 4)

__global__ __launch_bounds__(256) void attn_kernel()
{
    extern __shared__ unsigned sm_u[];
    unsigned* K_s = sm_u;                 // [64 key][68]  tf32
    unsigned* V_s = sm_u + 64*68;         // [64 key][72]  tf32
    unsigned* P_s = sm_u + 64*68 + 64*72; // 8 warps x [16][68] tf32
    unsigned* Q_s = sm_u;                 // [128][68] overlay (phase A only)

    const int qt = blockIdx.x, h = blockIdx.y, b = blockIdx.z;
    const int tid  = threadIdx.x;
    const int wid  = tid >> 5;
    const int lane = tid & 31;
    const int g    = lane >> 2;
    const int t    = lane & 3;

    const size_t head_off = (((size_t)b*HH + h)*SS) * DHH;
    const float* qbase = g_q + head_off;
    const float* kbase = g_k + head_off;
    const float* vbase = g_v + head_off;

    // ---- phase A: Q tile 128x64 -> smem (scaled, tf32), extract frags ----
    #pragma unroll
    for (int l = 0; l < 8; l++) {
        int idx = tid + l * 256;          // 2048 float4
        int i = idx >> 4;
        int j = (idx & 15) << 2;
        float4 q4 = *reinterpret_cast<const float4*>(qbase + (size_t)(qt*128 + i)*DHH + j);
        unsigned* p = &Q_s[i*68 + j];
        p[0] = f2t(q4.x * 0.125f); p[1] = f2t(q4.y * 0.125f);
        p[2] = f2t(q4.z * 0.125f); p[3] = f2t(q4.w * 0.125f);
    }
    __syncthreads();

    unsigned qf[8][4];
    {
        int rb = wid*16 + g;
        #pragma unroll
        for (int ks = 0; ks < 8; ks++) {
            qf[ks][0] = Q_s[(rb  )*68 + ks*8 + t];
            qf[ks][1] = Q_s[(rb+8)*68 + ks*8 + t];
            qf[ks][2] = Q_s[(rb  )*68 + ks*8 + t + 4];
            qf[ks][3] = Q_s[(rb+8)*68 + ks*8 + t + 4];
        }
    }
    __syncthreads();   // Q_s region about to be overwritten by K_s/V_s

    float octx[8][4] = {};
    float m_lo = -INFINITY, m_hi = -INFINITY;
    float l_lo = 0.f, l_hi = 0.f;

    unsigned* P_w = P_s + wid*16*68;

    for (int kt = 0; kt < KT; kt++) {
        // ---- load K and V tiles (64x64 each) ----
        #pragma unroll
        for (int l = 0; l < 4; l++) {
            int idx = tid + l * 256;      // 1024 float4
            int i = idx >> 4;
            int j = (idx & 15) << 2;
            float4 k4 = *reinterpret_cast<const float4*>(kbase + (size_t)(kt*64 + i)*DHH + j);
            unsigned* pk = &K_s[i*68 + j];
            pk[0] = f2t(k4.x); pk[1] = f2t(k4.y); pk[2] = f2t(k4.z); pk[3] = f2t(k4.w);
            float4 v4 = *reinterpret_cast<const float4*>(vbase + (size_t)(kt*64 + i)*DHH + j);
            unsigned* pv = &V_s[i*72 + j];
            pv[0] = f2t(v4.x); pv[1] = f2t(v4.y); pv[2] = f2t(v4.z); pv[3] = f2t(v4.w);
        }
        __syncthreads();

        // ---- S = Q @ K^T : warp computes 16x64 scores ----
        float sacc[8][4] = {};
        #pragma unroll
        for (int ks = 0; ks < 8; ks++) {
            #pragma unroll
            for (int nt = 0; nt < 8; nt++) {
                unsigned b0 = K_s[(nt*8 + g)*68 + ks*8 + t];
                unsigned b1 = K_s[(nt*8 + g)*68 + ks*8 + t + 4];
                mma8(sacc[nt], qf[ks], b0, b1);
            }
        }

        // ---- warp-local online softmax ----
        float tmax_lo = -INFINITY, tmax_hi = -INFINITY;
        #pragma unroll
        for (int nt = 0; nt < 8; nt++) {
            tmax_lo = fmaxf(tmax_lo, fmaxf(sacc[nt][0], sacc[nt][1]));
            tmax_hi = fmaxf(tmax_hi, fmaxf(sacc[nt][2], sacc[nt][3]));
        }
        tmax_lo = fmaxf(tmax_lo, __shfl_xor_sync(0xffffffffu, tmax_lo, 1));
        tmax_lo = fmaxf(tmax_lo, __shfl_xor_sync(0xffffffffu, tmax_lo, 2));
        tmax_hi = fmaxf(tmax_hi, __shfl_xor_sync(0xffffffffu, tmax_hi, 1));
        tmax_hi = fmaxf(tmax_hi, __shfl_xor_sync(0xffffffffu, tmax_hi, 2));

        float newm_lo = fmaxf(m_lo, tmax_lo);
        float newm_hi = fmaxf(m_hi, tmax_hi);
        float cf_lo = __expf(m_lo - newm_lo);   // 0 on first tile
        float cf_hi = __expf(m_hi - newm_hi);
        m_lo = newm_lo; m_hi = newm_hi;

        float psum_lo = 0.f, psum_hi = 0.f;
        #pragma unroll
        for (int nt = 0; nt < 8; nt++) {
            float p0 = __expf(sacc[nt][0] - newm_lo);
            float p1 = __expf(sacc[nt][1] - newm_lo);
            float p2 = __expf(sacc[nt][2] - newm_hi);
            float p3 = __expf(sacc[nt][3] - newm_hi);
            psum_lo += p0 + p1;
            psum_hi += p2 + p3;
            // store exp'd probs (tf32 bits) to per-warp P buffer
            uint2 lo = make_uint2(f2t(p0), f2t(p1));
            uint2 hi = make_uint2(f2t(p2), f2t(p3));
            *reinterpret_cast<uint2*>(&P_w[(g  )*68 + nt*8 + 2*t]) = lo;
            *reinterpret_cast<uint2*>(&P_w[(g+8)*68 + nt*8 + 2*t]) = hi;
        }
        psum_lo += __shfl_xor_sync(0xffffffffu, psum_lo, 1);
        psum_lo += __shfl_xor_sync(0xffffffffu, psum_lo, 2);
        psum_hi += __shfl_xor_sync(0xffffffffu, psum_hi, 1);
        psum_hi += __shfl_xor_sync(0xffffffffu, psum_hi, 2);
        l_lo = l_lo * cf_lo + psum_lo;
        l_hi = l_hi * cf_hi + psum_hi;

        // rescale running context
        #pragma unroll
        for (int nt = 0; nt < 8; nt++) {
            octx[nt][0] *= cf_lo; octx[nt][1] *= cf_lo;
            octx[nt][2] *= cf_hi; octx[nt][3] *= cf_hi;
        }
        __syncwarp();   // P_w stores visible to whole warp

        // ---- ctx += P @ V : warp 16x64 ----
        #pragma unroll
        for (int ks = 0; ks < 8; ks++) {
            unsigned pa[4];
            pa[0] = P_w[(g  )*68 + ks*8 + t];
            pa[1] = P_w[(g+8)*68 + ks*8 + t];
            pa[2] = P_w[(g  )*68 + ks*8 + t + 4];
            pa[3] = P_w[(g+8)*68 + ks*8 + t + 4];
            #pragma unroll
            for (int nt = 0; nt < 8; nt++) {
                // B[k=key][n=dh] direct from natural V layout
                unsigned b0 = V_s[(ks*8 + t    )*72 + nt*8 + g];
                unsigned b1 = V_s[(ks*8 + t + 4)*72 + nt*8 + g];
                mma8(octx[nt], pa, b0, b1);
            }
        }
        __syncthreads();   // before K_s/V_s overwritten
    }

    // ---- epilogue: normalize, write ctx in [B,S,D] layout ----
    float inv_lo = 1.f / l_lo;
    float inv_hi = 1.f / l_hi;
    int s_lo = qt*128 + wid*16 + g;
    int s_hi = s_lo + 8;
    #pragma unroll
    for (int nt = 0; nt < 8; nt++) {
        int col = h*DHH + nt*8 + 2*t;
        float2 o_lo = make_float2(octx[nt][0]*inv_lo, octx[nt][1]*inv_lo);
        float2 o_hi = make_float2(octx[nt][2]*inv_hi, octx[nt][3]*inv_hi);
        *reinterpret_cast<float2*>(g_ctx + ((size_t)b*SS + s_lo)*DD + col) = o_lo;
        *reinterpret_cast<float2*>(g_ctx + ((size_t)b*SS + s_hi)*DD + col) = o_hi;
    }
}

// ---------------------------------------------------------------------------
// Kernel 3: output projection out = ctx @ Wo + bo (tensor cores, tf32).
// grid = (NROW/256, D/64), block = 256. Same tiling as qkv.
// ---------------------------------------------------------------------------
__global__ __launch_bounds__(256) void proj_kernel(
    const float* __restrict__ Wo, const float* __restrict__ bo,
    float* __restrict__ out)
{
    __shared__ unsigned A_s[256*36];
    __shared__ unsigned B_s[64*36];

    const int tid  = threadIdx.x;
    const int wid  = tid >> 5;
    const int lane = tid & 31;
    const int g    = lane >> 2;
    const int t    = lane & 3;
    const int r0   = blockIdx.x * 256;
    const int n0   = blockIdx.y * 64;

    float acc[2][8][4] = {};

    for (int kk = 0; kk < DD; kk += 32) {
        #pragma unroll
        for (int l = 0; l < 8; l++) {
            int idx = tid + l * 256;
            int i = idx >> 3;
            int j = (idx & 7) << 2;
            float4 a4 = *reinterpret_cast<const float4*>(g_ctx + (size_t)(r0 + i)*DD + kk + j);
            unsigned* p = &A_s[i*36 + j];
            p[0] = f2t(a4.x); p[1] = f2t(a4.y); p[2] = f2t(a4.z); p[3] = f2t(a4.w);
        }
        #pragma unroll
        for (int l = 0; l < 2; l++) {
            int idx = tid + l * 256;
            int d = idx >> 4;
            int e = (idx & 15) << 2;
            float4 w4 = *reinterpret_cast<const float4*>(Wo + (size_t)(kk + d)*DD + n0 + e);
            B_s[(e+0)*36 + d] = f2t(w4.x);
            B_s[(e+1)*36 + d] = f2t(w4.y);
            B_s[(e+2)*36 + d] = f2t(w4.z);
            B_s[(e+3)*36 + d] = f2t(w4.w);
        }
        __syncthreads();

        #pragma unroll
        for (int ks = 0; ks < 4; ks++) {
            int k8 = ks * 8;
            unsigned a[2][4];
            #pragma unroll
            for (int mt = 0; mt < 2; mt++) {
                int rb = wid*32 + mt*16 + g;
                a[mt][0] = A_s[(rb  )*36 + k8 + t];
                a[mt][1] = A_s[(rb+8)*36 + k8 + t];
                a[mt][2] = A_s[(rb  )*36 + k8 + t + 4];
                a[mt][3] = A_s[(rb+8)*36 + k8 + t + 4];
            }
            #pragma unroll
            for (int nt = 0; nt < 8; nt++) {
                unsigned b0 = B_s[(nt*8 + g)*36 + k8 + t];
                unsigned b1 = B_s[(nt*8 + g)*36 + k8 + t + 4];
                mma8(acc[0][nt], a[0], b0, b1);
                mma8(acc[1][nt], a[1], b0, b1);
            }
        }
        __syncthreads();
    }

    #pragma unroll
    for (int mt = 0; mt < 2; mt++) {
        #pragma unroll
        for (int nt = 0; nt < 8; nt++) {
            int col = n0 + nt*8 + 2*t;
            float b0 = bo[col], b1 = bo[col+1];
            int r_lo = r0 + wid*32 + mt*16 + g;
            int r_hi = r_lo + 8;
            float2 o_lo = make_float2(acc[mt][nt][0] + b0, acc[mt][nt][1] + b1);
            float2 o_hi = make_float2(acc[mt][nt][2] + b0, acc[mt][nt][3] + b1);
            *reinterpret_cast<float2*>(out + (size_t)r_lo*DD + col) = o_lo;
            *reinterpret_cast<float2*>(out + (size_t)r_hi*DD + col) = o_hi;
        }
    }
}

// ---------------------------------------------------------------------------
extern "C" void kernel_launch(void* const* d_in, const int* in_sizes, int n_in,
                              void* d_out, int out_size)
{
    const float* x  = (const float*)d_in[0];
    const float* Wq = (const float*)d_in[1];
    const float* bq = (const float*)d_in[2];
    const float* Wk = (const float*)d_in[3];
    const float* bk = (const float*)d_in[4];
    const float* Wv = (const float*)d_in[5];
    const float* bv = (const float*)d_in[6];
    const float* Wo = (const float*)d_in[7];
    const float* bo = (const float*)d_in[8];
    float* out = (float*)d_out;

    cudaFuncSetAttribute(attn_kernel,
                         cudaFuncAttributeMaxDynamicSharedMemorySize,
                         ATTN_SMEM_BYTES);

    qkv_kernel<<<dim3(NROW/256, HH, 3), 256>>>(x, Wq, bq, Wk, bk, Wv, bv);
    attn_kernel<<<dim3(SS/128, HH, BB), 256, ATTN_SMEM_BYTES>>>();
    proj_kernel<<<dim3(NROW/256, DD/64), 256>>>(Wo, bo, out);
}